// round 17
// baseline (speedup 1.0000x reference)
#include <cuda_runtime.h>
#include <cstdint>

#define TT 2048
#define BB 8
#define CC 1024
#define HH 64

#define NSPLIT 4

typedef unsigned long long u64;

__device__ __forceinline__ uint32_t cvt_tf32(float v) {
    uint32_t t; asm("cvt.rna.tf32.f32 %0, %1;" : "=r"(t) : "f"(v)); return t;
}
__device__ __forceinline__ uint32_t smem_u32(const void* p) {
    uint32_t a;
    asm("{ .reg .u64 t; cvta.to.shared.u64 t, %1; cvt.u32.u64 %0, t; }" : "=r"(a) : "l"(p));
    return a;
}
// HMMA tf32: D(16x8) += A(16x8) * B(8x8); base ISA (sm_80+).
__device__ __forceinline__ void mma_tf32(float* c, const uint32_t* a,
                                         uint32_t b0, uint32_t b1) {
    asm volatile(
        "mma.sync.aligned.m16n8k8.row.col.f32.tf32.tf32.f32 "
        "{%0,%1,%2,%3}, {%4,%5,%6,%7}, {%8,%9}, {%0,%1,%2,%3};"
        : "+f"(c[0]), "+f"(c[1]), "+f"(c[2]), "+f"(c[3])
        : "r"(a[0]), "r"(a[1]), "r"(a[2]), "r"(a[3]), "r"(b0), "r"(b1));
}
__device__ __forceinline__ void ldsm_x4(uint32_t* r, uint32_t addr) {
    asm volatile("ldmatrix.sync.aligned.m8n8.x4.shared.b16 {%0,%1,%2,%3}, [%4];"
                 : "=r"(r[0]), "=r"(r[1]), "=r"(r[2]), "=r"(r[3]) : "r"(addr));
}

// Scratch: projected q/k/v [B,T,H] fp32 + split-K partials (4 ways).
__device__ float g_q[BB * TT * HH];
__device__ float g_k[BB * TT * HH];
__device__ float g_v[BB * TT * HH];
__device__ float g_po[NSPLIT * BB * TT * HH];
__device__ float g_pm[NSPLIT * BB * TT];
__device__ float g_pl[NSPLIT * BB * TT];

// ---------------------------------------------------------------------------
// Kernel 1: tf32 HMMA QKV projection (round-12 config: measured fastest).
// CTA = 128 rows x 192 cols, 8 warps (warp tile 32 x 96 = 2 m16 x 12 n8),
// K chunks of 32 in smem, register-prefetch double buffering. Grid 128.
// ---------------------------------------------------------------------------
__global__ __launch_bounds__(256) void proj_kernel(
    const float* __restrict__ x,
    const float* __restrict__ Wq,
    const float* __restrict__ Wk,
    const float* __restrict__ Wv)
{
    __shared__ uint32_t As[128][36];   // [m][k], tf32 bits
    __shared__ uint32_t Bs[32][200];   // [k][n], tf32 bits

    const int tid = threadIdx.x;
    const int wid = tid >> 5;
    const int lane = tid & 31;
    const int g = lane >> 2;
    const int t = lane & 3;
    const int wr = wid & 3;           // 4 x 32 rows
    const int wc = wid >> 2;          // 2 x 96 cols
    const int row0 = blockIdx.x * 128;

    float c[2][12][4];
#pragma unroll
    for (int mi = 0; mi < 2; mi++)
#pragma unroll
        for (int j = 0; j < 12; j++)
#pragma unroll
            for (int q = 0; q < 4; q++) c[mi][j][q] = 0.f;

    const int ar = tid >> 3;                // 0..31 base rows (x4 via +32*i)
    const int ac = (tid & 7) * 4;
    int br[6], bc[6];
    const float* wsrc[6];
#pragma unroll
    for (int i = 0; i < 6; i++) {
        int idx = tid + 256 * i;
        br[i] = idx / 48;
        bc[i] = (idx - br[i] * 48) * 4;
        int sgm = bc[i] >> 6;
        const float* W = (sgm == 0) ? Wq : (sgm == 1) ? Wk : Wv;
        wsrc[i] = W + (bc[i] & 63);
    }

    float4 pa[4], pb[6];
#pragma unroll
    for (int i = 0; i < 4; i++)
        pa[i] = *(const float4*)&x[(size_t)(row0 + ar + 32 * i) * CC + ac];
#pragma unroll
    for (int i = 0; i < 6; i++)
        pb[i] = *(const float4*)(wsrc[i] + (size_t)br[i] * 64);

    const uint32_t As_b = smem_u32(&As[0][0]);
    const uint32_t lrow = wr * 32 + (lane & 15);
    const uint32_t lcol = (lane >> 4) * 4;

    for (int kc = 0; kc < 32; kc++) {
        if (kc) __syncthreads();

#pragma unroll
        for (int i = 0; i < 4; i++) {
            uint32_t* d = &As[ar + 32 * i][ac];
            d[0] = cvt_tf32(pa[i].x); d[1] = cvt_tf32(pa[i].y);
            d[2] = cvt_tf32(pa[i].z); d[3] = cvt_tf32(pa[i].w);
        }
#pragma unroll
        for (int i = 0; i < 6; i++) {
            uint32_t* d = &Bs[br[i]][bc[i]];
            d[0] = cvt_tf32(pb[i].x); d[1] = cvt_tf32(pb[i].y);
            d[2] = cvt_tf32(pb[i].z); d[3] = cvt_tf32(pb[i].w);
        }
        __syncthreads();

        if (kc + 1 < 32) {
            const int k1 = (kc + 1) * 32;
#pragma unroll
            for (int i = 0; i < 4; i++)
                pa[i] = *(const float4*)&x[(size_t)(row0 + ar + 32 * i) * CC + k1 + ac];
#pragma unroll
            for (int i = 0; i < 6; i++)
                pb[i] = *(const float4*)(wsrc[i] + (size_t)(k1 + br[i]) * 64);
        }

#pragma unroll
        for (int s = 0; s < 4; s++) {
            uint32_t afr[2][4];
#pragma unroll
            for (int mi = 0; mi < 2; mi++)
                ldsm_x4(afr[mi], As_b + ((lrow + mi * 16) * 36 + s * 8 + lcol) * 4);
#pragma unroll
            for (int j = 0; j < 12; j++) {
                int col = wc * 96 + j * 8 + g;
                uint32_t b0 = Bs[s * 8 + t][col];
                uint32_t b1 = Bs[s * 8 + t + 4][col];
                mma_tf32(c[0][j], afr[0], b0, b1);
                mma_tf32(c[1][j], afr[1], b0, b1);
            }
        }
    }

#pragma unroll
    for (int mi = 0; mi < 2; mi++) {
        int rb = row0 + wr * 32 + mi * 16;
#pragma unroll
        for (int j = 0; j < 12; j++) {
            int cb = wc * 96 + j * 8;
            int seg = cb >> 6;
            int off = (cb & 63) + 2 * t;
            float* base = (seg == 0) ? g_q : (seg == 1) ? g_k : g_v;
            float2 v0; v0.x = c[mi][j][0]; v0.y = c[mi][j][1];
            float2 v1; v1.x = c[mi][j][2]; v1.y = c[mi][j][3];
            *(float2*)&base[(size_t)(rb + g) * 64 + off] = v0;
            *(float2*)&base[(size_t)(rb + g + 8) * 64 + off] = v1;
        }
    }
}

// ---------------------------------------------------------------------------
// Kernel 2: 4-way split-K flash attention, fully tensorized.
// ss aliased onto qs (dead after Q-fragment preload): smem 34.5 KB.
// __launch_bounds__(128, 5): 5 resident CTAs/SM to hide the per-tile
// dependent chain. K/V + rbias register prefetch.
// ---------------------------------------------------------------------------
__global__ __launch_bounds__(128, 5) void attn_kernel(
    const float* __restrict__ rbias)
{
    __shared__ uint32_t qs[64][68];    // tf32 Q bits; later reused as ss[64][36]
    __shared__ uint32_t ks[32][68];    // tf32 bits, [key][h]
    __shared__ uint32_t vs[32][72];    // tf32 bits, [key][h]
    uint32_t (*ss)[36] = reinterpret_cast<uint32_t(*)[36]>(&qs[0][0]);

    const int b = blockIdx.y;
    const int half = blockIdx.z;         // 0..3
    const int qb = 31 - blockIdx.x;      // heavy tiles first
    const int q0 = qb * 64;
    const int tid = threadIdx.x;
    const int w = tid >> 5;
    const int lane = tid & 31;
    const int gq = lane >> 2;            // 0..7
    const int t = lane & 3;              // 0..3

    // Load Q tile (64 x 64) -> qs tf32
#pragma unroll
    for (int i = 0; i < 8; i++) {
        int idx = tid + 128 * i;
        int r = idx >> 4, hs = (idx & 15) * 4;
        float4 v = *(const float4*)&g_q[((size_t)(b * TT + q0 + r)) * HH + hs];
        uint32_t* d = &qs[r][hs];
        d[0] = cvt_tf32(v.x); d[1] = cvt_tf32(v.y);
        d[2] = cvt_tf32(v.z); d[3] = cvt_tf32(v.w);
    }
    __syncthreads();

    const uint32_t lrow = w * 16 + (lane & 15);
    const uint32_t lcol = (lane >> 4) * 4;

    // Preload Q fragments for all 8 k8-steps (qs dead afterwards)
    uint32_t qfr[8][4];
    {
        const uint32_t qs_b = smem_u32(&qs[0][0]);
#pragma unroll
        for (int s = 0; s < 8; s++)
            ldsm_x4(qfr[s], qs_b + (lrow * 68 + s * 8 + lcol) * 4);
    }
    const uint32_t ss_b = smem_u32(&qs[0][0]);   // ss aliases qs

    const int rA = w * 16 + gq;
    const int rB = rA + 8;
    const int qiA = q0 + rA, qiB = q0 + rB;
    float m0 = -1e30f, m1 = -1e30f, l0 = 0.f, l1 = 0.f;

    float opv[8][4];
#pragma unroll
    for (int j = 0; j < 8; j++)
#pragma unroll
        for (int q = 0; q < 4; q++) opv[j][q] = 0.f;

    const int nkb = 2 * qb + 2;
    const int kb_beg = (half * nkb) / NSPLIT;
    const int kb_end = ((half + 1) * nkb) / NSPLIT;

    // per-thread K/V load coordinates (fixed)
    int ldr[4], ldh[4];
#pragma unroll
    for (int i = 0; i < 4; i++) {
        int idx = tid + 128 * i;
        ldr[i] = idx >> 4;
        ldh[i] = (idx & 15) * 4;
    }

    // prefetch first tile into registers (valid addr even if range empty)
    float4 pk[4], pv[4];
    {
        const int k0 = kb_beg * 32;
#pragma unroll
        for (int i = 0; i < 4; i++) {
            size_t gi = ((size_t)(b * TT + k0 + ldr[i])) * HH + ldh[i];
            pk[i] = *(const float4*)&g_k[gi];
            pv[i] = *(const float4*)&g_v[gi];
        }
    }

    for (int kb = kb_beg; kb < kb_end; kb++) {
        const int k0 = kb * 32;
        __syncthreads();   // previous S/PV reads of ks/vs/ss done

        // store prefetched K/V (cvt to tf32)
#pragma unroll
        for (int i = 0; i < 4; i++) {
            uint32_t* kd = &ks[ldr[i]][ldh[i]];
            kd[0] = cvt_tf32(pk[i].x); kd[1] = cvt_tf32(pk[i].y);
            kd[2] = cvt_tf32(pk[i].z); kd[3] = cvt_tf32(pk[i].w);
            uint32_t* vd = &vs[ldr[i]][ldh[i]];
            vd[0] = cvt_tf32(pv[i].x); vd[1] = cvt_tf32(pv[i].y);
            vd[2] = cvt_tf32(pv[i].z); vd[3] = cvt_tf32(pv[i].w);
        }
        __syncthreads();

        // prefetch next tile (LDGs in flight during compute)
        if (kb + 1 < kb_end) {
            const int k1 = k0 + 32;
#pragma unroll
            for (int i = 0; i < 4; i++) {
                size_t gi = ((size_t)(b * TT + k1 + ldr[i])) * HH + ldh[i];
                pk[i] = *(const float4*)&g_k[gi];
                pv[i] = *(const float4*)&g_v[gi];
            }
        }

        // rbias prefetch
        float2 rba[4], rbb[4];
#pragma unroll
        for (int j = 0; j < 4; j++) {
            int kj = k0 + j * 8 + 2 * t;
            rba[j] = *(const float2*)&rbias[(size_t)qiA * TT + kj];
            rbb[j] = *(const float2*)&rbias[(size_t)qiB * TT + kj];
        }

        // S = Q K^T : per warp m16 x n32, 8 k8 steps
        float c[4][4];
#pragma unroll
        for (int j = 0; j < 4; j++)
#pragma unroll
            for (int q = 0; q < 4; q++) c[j][q] = 0.f;
#pragma unroll
        for (int s = 0; s < 8; s++) {
#pragma unroll
            for (int j = 0; j < 4; j++) {
                uint32_t b0 = ks[j * 8 + gq][s * 8 + t];
                uint32_t b1 = ks[j * 8 + gq][s * 8 + t + 4];
                mma_tf32(c[j], qfr[s], b0, b1);
            }
        }

        // Softmax epilogue in fragment layout
        float sA[8], sB[8];
        float mxA = -1e30f, mxB = -1e30f;
#pragma unroll
        for (int j = 0; j < 4; j++) {
            int kj = k0 + j * 8 + 2 * t;
            bool a0 = (kj <= qiA) && (rba[j].x > 0.f || kj == qiA);
            bool a1 = (kj + 1 <= qiA) && (rba[j].y > 0.f || kj + 1 == qiA);
            bool b0k = (kj <= qiB) && (rbb[j].x > 0.f || kj == qiB);
            bool b1k = (kj + 1 <= qiB) && (rbb[j].y > 0.f || kj + 1 == qiB);
            sA[2 * j]     = a0 ? fmaf(c[j][0], 0.03125f, rba[j].x) : -1e30f;
            sA[2 * j + 1] = a1 ? fmaf(c[j][1], 0.03125f, rba[j].y) : -1e30f;
            sB[2 * j]     = b0k ? fmaf(c[j][2], 0.03125f, rbb[j].x) : -1e30f;
            sB[2 * j + 1] = b1k ? fmaf(c[j][3], 0.03125f, rbb[j].y) : -1e30f;
            mxA = fmaxf(mxA, fmaxf(sA[2 * j], sA[2 * j + 1]));
            mxB = fmaxf(mxB, fmaxf(sB[2 * j], sB[2 * j + 1]));
        }
        mxA = fmaxf(mxA, __shfl_xor_sync(0xffffffffu, mxA, 1));
        mxA = fmaxf(mxA, __shfl_xor_sync(0xffffffffu, mxA, 2));
        mxB = fmaxf(mxB, __shfl_xor_sync(0xffffffffu, mxB, 1));
        mxB = fmaxf(mxB, __shfl_xor_sync(0xffffffffu, mxB, 2));

        float mA = fmaxf(m0, mxA), mB = fmaxf(m1, mxB);
        float baseA = fmaxf(mA, -1e28f), baseB = fmaxf(mB, -1e28f);
        float crA = __expf(m0 - mA), crB = __expf(m1 - mB);
        m0 = mA; m1 = mB;
        float sumA = 0.f, sumB = 0.f;
#pragma unroll
        for (int jj = 0; jj < 8; jj++) {
            float pA = __expf(sA[jj] - baseA);
            float pB = __expf(sB[jj] - baseB);
            sumA += pA; sumB += pB;
            sA[jj] = pA; sB[jj] = pB;
        }
#pragma unroll
        for (int j = 0; j < 4; j++) {
            uint2 wa; wa.x = cvt_tf32(sA[2 * j]); wa.y = cvt_tf32(sA[2 * j + 1]);
            uint2 wb; wb.x = cvt_tf32(sB[2 * j]); wb.y = cvt_tf32(sB[2 * j + 1]);
            *(uint2*)&ss[rA][j * 8 + 2 * t] = wa;
            *(uint2*)&ss[rB][j * 8 + 2 * t] = wb;
        }
        sumA += __shfl_xor_sync(0xffffffffu, sumA, 1);
        sumA += __shfl_xor_sync(0xffffffffu, sumA, 2);
        sumB += __shfl_xor_sync(0xffffffffu, sumB, 1);
        sumB += __shfl_xor_sync(0xffffffffu, sumB, 2);
        l0 = l0 * crA + sumA;
        l1 = l1 * crB + sumB;
        __syncwarp();

        // rescale O by corr
#pragma unroll
        for (int j = 0; j < 8; j++) {
            opv[j][0] *= crA; opv[j][1] *= crA;
            opv[j][2] *= crB; opv[j][3] *= crB;
        }

        // PV: A = P (ldmatrix, warp-private rows), B = V
#pragma unroll
        for (int s = 0; s < 4; s++) {
            uint32_t pfr[4];
            ldsm_x4(pfr, ss_b + (lrow * 36 + s * 8 + lcol) * 4);
#pragma unroll
            for (int j = 0; j < 8; j++) {
                uint32_t b0 = vs[s * 8 + t][j * 8 + gq];
                uint32_t b1 = vs[s * 8 + t + 4][j * 8 + gq];
                mma_tf32(opv[j], pfr, b0, b1);
            }
        }
    }

    // epilogue: write unnormalized partials + (m, l)
    const size_t hoff = (size_t)half * (BB * TT * HH);
    const size_t rowA = (size_t)(b * TT) + qiA;
    const size_t rowB = (size_t)(b * TT) + qiB;
#pragma unroll
    for (int j = 0; j < 8; j++) {
        int col = j * 8 + 2 * t;
        float2 va; va.x = opv[j][0]; va.y = opv[j][1];
        float2 vb; vb.x = opv[j][2]; vb.y = opv[j][3];
        *(float2*)&g_po[hoff + rowA * HH + col] = va;
        *(float2*)&g_po[hoff + rowB * HH + col] = vb;
    }
    if (t == 0) {
        g_pm[half * (BB * TT) + rowA] = m0;
        g_pl[half * (BB * TT) + rowA] = l0;
        g_pm[half * (BB * TT) + rowB] = m1;
        g_pl[half * (BB * TT) + rowB] = l1;
    }
}

// ---------------------------------------------------------------------------
// Kernel 3: merge the 4 split-K partials and normalize.
// Empty partial ranges have m=-1e30 -> weight exp(m-mm)=0: safe.
// ---------------------------------------------------------------------------
__global__ __launch_bounds__(256) void combine_kernel(float* __restrict__ out)
{
    int idx = blockIdx.x * 256 + threadIdx.x;
    int e = idx * 4;
    int row = e >> 6;

    float pm[NSPLIT], pl[NSPLIT];
    float mm = -1e30f;
#pragma unroll
    for (int h = 0; h < NSPLIT; h++) {
        pm[h] = g_pm[h * (BB * TT) + row];
        pl[h] = g_pl[h * (BB * TT) + row];
        mm = fmaxf(mm, pm[h]);
    }
    float L = 0.f, a[NSPLIT];
#pragma unroll
    for (int h = 0; h < NSPLIT; h++) {
        a[h] = __expf(pm[h] - mm);
        L += pl[h] * a[h];
    }
    float inv = 1.f / L;

    float4 acc; acc.x = 0.f; acc.y = 0.f; acc.z = 0.f; acc.w = 0.f;
#pragma unroll
    for (int h = 0; h < NSPLIT; h++) {
        float4 xv = *(const float4*)&g_po[(size_t)h * (BB * TT * HH) + e];
        acc.x = fmaf(xv.x, a[h], acc.x);
        acc.y = fmaf(xv.y, a[h], acc.y);
        acc.z = fmaf(xv.z, a[h], acc.z);
        acc.w = fmaf(xv.w, a[h], acc.w);
    }
    acc.x *= inv; acc.y *= inv; acc.z *= inv; acc.w *= inv;
    *(float4*)&out[e] = acc;
}

// ---------------------------------------------------------------------------
// Inputs (metadata order): x, Wq, Wk, Wv, rbias, allowed
// Output: [B, T, H] float32
// ---------------------------------------------------------------------------
extern "C" void kernel_launch(void* const* d_in, const int* in_sizes, int n_in,
                              void* d_out, int out_size)
{
    const float* x     = (const float*)d_in[0];
    const float* Wq    = (const float*)d_in[1];
    const float* Wk    = (const float*)d_in[2];
    const float* Wv    = (const float*)d_in[3];
    const float* rbias = (const float*)d_in[4];
    float* out = (float*)d_out;

    proj_kernel<<<128, 256>>>(x, Wq, Wk, Wv);
    attn_kernel<<<dim3(32, 8, NSPLIT), 128>>>(rbias);
    combine_kernel<<<1024, 256>>>(out);
}